// round 11
// baseline (speedup 1.0000x reference)
#include <cuda_runtime.h>
#include <cuda_fp16.h>
#include <cstdint>

#define B_ 8
#define C_ 256
#define H_ 128
#define W_ 128
#define HW_ (H_*W_)            // 16384
#define NPLANE (B_*C_)         // 2048
#define K_ 1280
#define O_ 256

#define NEG_INF __int_as_float(0xff800000)

// fp16 scratch: x copy + 2 H-direction max tensors + transposed weights.
// (W-direction scans are fused into the GEMM and never touch DRAM.)
__device__ __half g_x16[NPLANE*HW_];
__device__ __half g_dir16[2][NPLANE*HW_];
__device__ __half g_wT16[K_*O_];

// ------------------------------------------------------------------
// helpers
// ------------------------------------------------------------------
__device__ __forceinline__ uint32_t smem_u32(const void* p) {
    return (uint32_t)__cvta_generic_to_shared(p);
}
__device__ __forceinline__ void cp16(uint32_t s, const void* g) {
    asm volatile("cp.async.cg.shared.global [%0], [%1], 16;\n" :: "r"(s), "l"(g));
}
__device__ __forceinline__ void ldsm_x4_t(uint32_t& d0, uint32_t& d1,
                                          uint32_t& d2, uint32_t& d3, uint32_t a) {
    asm volatile("ldmatrix.sync.aligned.m8n8.x4.trans.shared.b16 {%0,%1,%2,%3},[%4];\n"
                 : "=r"(d0), "=r"(d1), "=r"(d2), "=r"(d3) : "r"(a));
}
__device__ __forceinline__ void mma_f16(float* d, const uint32_t* a, const uint32_t* b) {
    asm volatile(
        "mma.sync.aligned.m16n8k16.row.col.f32.f16.f16.f32 "
        "{%0,%1,%2,%3},{%4,%5,%6,%7},{%8,%9},{%0,%1,%2,%3};"
        : "+f"(d[0]), "+f"(d[1]), "+f"(d[2]), "+f"(d[3])
        : "r"(a[0]), "r"(a[1]), "r"(a[2]), "r"(a[3]), "r"(b[0]), "r"(b[1]));
}
__device__ __forceinline__ uint32_t h2u(__half2 h) {
    return *reinterpret_cast<uint32_t*>(&h);
}

// ------------------------------------------------------------------
// kernel 0: transpose conv_w [O][K] -> wT16 [K][O]
// ------------------------------------------------------------------
__global__ void k_wt(const float* __restrict__ w) {
    int idx = blockIdx.x * 256 + threadIdx.x;
    if (idx < K_*O_) {
        int o = idx / K_;
        int k = idx - o*K_;
        g_wT16[k*O_ + o] = __float2half_rn(w[idx]);
    }
}

// ------------------------------------------------------------------
// kernel 1: H-direction maxes only + x16 copy. One plane per 128-thread CTA.
// Threads 0..63: prefix over 2-column pairs (half2 stores -> full 128B/warp).
// Threads 64..127: suffix. No smem. 2048 CTAs -> latency fully hidden.
// ------------------------------------------------------------------
__global__ void __launch_bounds__(128) k_dir(const float* __restrict__ x) {
    int plane = blockIdx.x;
    const float* src = x + (size_t)plane*HW_;
    int tid = threadIdx.x;

    if (tid < 64) {
        int w2 = tid*2;
        __half* x16 = g_x16 + (size_t)plane*HW_;
        __half* d0  = g_dir16[0] + (size_t)plane*HW_;
        float m0 = NEG_INF, m1 = NEG_INF;
        #pragma unroll 8
        for (int h = 0; h < H_; ++h) {
            float2 v = __ldg(reinterpret_cast<const float2*>(src + h*W_ + w2));
            *reinterpret_cast<__half2*>(x16 + h*W_ + w2) = __floats2half2_rn(v.x, v.y);
            m0 = fmaxf(m0, v.x); m1 = fmaxf(m1, v.y);
            *reinterpret_cast<__half2*>(d0 + h*W_ + w2) = __floats2half2_rn(m0, m1);
        }
    } else {
        int w2 = (tid - 64)*2;
        __half* d1 = g_dir16[1] + (size_t)plane*HW_;
        float m0 = NEG_INF, m1 = NEG_INF;
        #pragma unroll 8
        for (int h = H_-1; h >= 0; --h) {
            float2 v = __ldg(reinterpret_cast<const float2*>(src + h*W_ + w2));
            m0 = fmaxf(m0, v.x); m1 = fmaxf(m1, v.y);
            *reinterpret_cast<__half2*>(d1 + h*W_ + w2) = __floats2half2_rn(m0, m1);
        }
    }
}

// ------------------------------------------------------------------
// kernel 2: fp16 GEMM, all batches, W-scans fused in the producer.
// Pixel tile = one image row h (BM=128=W). k-tile order:
//   kt 0..7   region 0 (x16)      j=kt
//   kt 8..15  region 1 (cummaxH)  j=kt-8
//   kt 16..23 region 2 (sufmaxH)  j=kt-16
//   kt 24..39 pairs: even=(region3 cumW, j), odd=(region4 sufW, j), j=(kt-24)/2
// Regions 0-2: cp.async from fp16 scratch. Region 3: in-kernel warp scan from
// one fp32 x-row read (prefix -> STS now, suffix -> regs). Region 4: flush regs.
// ------------------------------------------------------------------
#define BM 128
#define BN 256
#define BK 32
#define STAGES 3
#define SA_LD 136
#define SB_LD 264
#define STG_HALVES (BK*SA_LD + BK*SB_LD)
#define GEMM_SMEM (STAGES*STG_HALVES*2)   // 76800 B

__device__ __forceinline__ void ktinfo(int kt, int& region, int& j) {
    if (kt < 24) { region = kt >> 3; j = kt & 7; }
    else { j = (kt - 24) >> 1; region = 3 + ((kt - 24) & 1); }
}

__global__ void __launch_bounds__(256, 1) k_gemm(const float* __restrict__ x,
                                                 const float* __restrict__ bias,
                                                 float* __restrict__ out) {
    extern __shared__ __half sm[];

    int tid  = threadIdx.x;
    int lane = tid & 31, warp = tid >> 5;
    int wm = warp >> 2, wn = warp & 3;
    int grp = lane >> 2, tig = lane & 3;
    int lr = lane & 7, lg = lane >> 3;

    int pixbase = blockIdx.x * BM;        // == row h * W
    int b       = blockIdx.y;

    size_t boff = (size_t)b * C_ * HW_;
    const __half* srcs[3] = { g_x16 + boff, g_dir16[0] + boff, g_dir16[1] + boff };
    const float* xb = x + boff;

    // cp.async part of a tile (A only for regions 0-2; B always)
    auto load_tile = [&](int kt, int st) {
        int region, j; ktinfo(kt, region, j);
        __half* sa = sm + st*STG_HALVES;
        __half* sb = sa + BK*SA_LD;
        if (region < 3) {
            const __half* aptr = srcs[region] + (size_t)(j*BK)*HW_ + pixbase;
            #pragma unroll
            for (int i = 0; i < 2; ++i) {
                int c  = tid + i*256;
                int kr = c >> 4, cc = c & 15;
                cp16(smem_u32(sa + kr*SA_LD + cc*8), aptr + (size_t)kr*HW_ + cc*8);
            }
        }
        const __half* bptr = g_wT16 + (size_t)((region*8 + j)*BK)*O_;
        #pragma unroll
        for (int i = 0; i < 4; ++i) {
            int c  = tid + i*256;
            int kr = c >> 5, cc = c & 31;
            cp16(smem_u32(sb + kr*SB_LD + cc*8), bptr + kr*O_ + cc*8);
        }
        asm volatile("cp.async.commit_group;\n" ::: "memory");
    };

    // held suffix-scan tile (4 channels/warp x 4 halves/lane = 8 x u32... 8 regs)
    uint32_t sufreg[8];

    // manual A producer for regions 3/4 (call AFTER __syncthreads)
    auto produce = [&](int p) {
        int region, j; ktinfo(p, region, j);
        if (region < 3) return;
        __half* sa = sm + (p % STAGES)*STG_HALVES;
        if (region == 3) {
            #pragma unroll
            for (int cc = 0; cc < 4; ++cc) {
                int ch = warp*4 + cc;
                const float* xrow = xb + (size_t)(j*BK + ch)*HW_ + pixbase;
                float4 v = __ldg(reinterpret_cast<const float4*>(xrow + 4*lane));

                // prefix (left->right)
                float p0 = v.x, p1 = fmaxf(v.y,p0), p2 = fmaxf(v.z,p1), p3 = fmaxf(v.w,p2);
                float agg = p3;
                #pragma unroll
                for (int d = 1; d < 32; d <<= 1) {
                    float t = __shfl_up_sync(0xffffffffu, agg, d);
                    if (lane >= d) agg = fmaxf(agg, t);
                }
                float prev = __shfl_up_sync(0xffffffffu, agg, 1);
                if (lane == 0) prev = NEG_INF;
                __half2 A  = __floats2half2_rn(fmaxf(p0,prev), fmaxf(p1,prev));
                __half2 Bh = __floats2half2_rn(fmaxf(p2,prev), fmaxf(p3,prev));
                *reinterpret_cast<uint2*>(sa + ch*SA_LD + 4*lane) =
                    make_uint2(h2u(A), h2u(Bh));

                // suffix (right->left) -> registers, flushed at region-4 tile
                float s3 = v.w, s2 = fmaxf(v.z,s3), s1 = fmaxf(v.y,s2), s0 = fmaxf(v.x,s1);
                float agg2 = s0;
                #pragma unroll
                for (int d = 1; d < 32; d <<= 1) {
                    float t = __shfl_down_sync(0xffffffffu, agg2, d);
                    if (lane + d < 32) agg2 = fmaxf(agg2, t);
                }
                float nxt = __shfl_down_sync(0xffffffffu, agg2, 1);
                if (lane == 31) nxt = NEG_INF;
                __half2 S0 = __floats2half2_rn(fmaxf(s0,nxt), fmaxf(s1,nxt));
                __half2 S1 = __floats2half2_rn(fmaxf(s2,nxt), fmaxf(s3,nxt));
                sufreg[cc*2]   = h2u(S0);
                sufreg[cc*2+1] = h2u(S1);
            }
        } else {  // region 4: flush held suffix tiles
            #pragma unroll
            for (int cc = 0; cc < 4; ++cc) {
                int ch = warp*4 + cc;
                *reinterpret_cast<uint2*>(sa + ch*SA_LD + 4*lane) =
                    make_uint2(sufreg[cc*2], sufreg[cc*2+1]);
            }
        }
    };

    float acc[4][8][4];
    #pragma unroll
    for (int i = 0; i < 4; ++i)
        #pragma unroll
        for (int j = 0; j < 8; ++j)
            #pragma unroll
            for (int r = 0; r < 4; ++r) acc[i][j][r] = 0.f;

    load_tile(0, 0);
    load_tile(1, 1);

    for (int kt = 0; kt < 40; ++kt) {
        int cur = kt % STAGES;
        if (kt + 2 < 40) {
            load_tile(kt + 2, (kt + 2) % STAGES);
            asm volatile("cp.async.wait_group 2;\n" ::: "memory");
        } else {
            asm volatile("cp.async.wait_group %0;\n" :: "n"(0) : "memory");
        }
        __syncthreads();

        uint32_t saU = smem_u32(sm + cur*STG_HALVES);
        uint32_t sbU = saU + BK*SA_LD*2;

        // fragment loads for tile kt
        uint32_t af[2][4][4];
        uint32_t bf[2][8][2];
        #pragma unroll
        for (int s = 0; s < 2; ++s) {
            int k0 = s*16;
            {
                int krow = k0 + lr + ((lg & 2) << 2);
                int cofs = (lg & 1) << 3;
                #pragma unroll
                for (int mf = 0; mf < 4; ++mf) {
                    int m0 = wm*64 + mf*16;
                    uint32_t a = saU + (uint32_t)(krow*SA_LD + m0 + cofs)*2;
                    ldsm_x4_t(af[s][mf][0], af[s][mf][1], af[s][mf][2], af[s][mf][3], a);
                }
            }
            {
                int krow = k0 + lr + ((lg & 1) << 3);
                int cofs = (lg >> 1) << 3;
                #pragma unroll
                for (int jp = 0; jp < 4; ++jp) {
                    int nj = wn*64 + jp*16;
                    uint32_t a = sbU + (uint32_t)(krow*SB_LD + nj + cofs)*2;
                    ldsm_x4_t(bf[s][2*jp][0], bf[s][2*jp][1],
                              bf[s][2*jp+1][0], bf[s][2*jp+1][1], a);
                }
            }
        }

        // manual A production for tile kt+2 (safe: stage freed by barrier above)
        if (kt + 2 < 40) produce(kt + 2);

        #pragma unroll
        for (int s = 0; s < 2; ++s)
            #pragma unroll
            for (int mf = 0; mf < 4; ++mf)
                #pragma unroll
                for (int nf = 0; nf < 8; ++nf)
                    mma_f16(acc[mf][nf], af[s][mf], bf[s][nf]);
        __syncthreads();
    }

    float* outb = out + (size_t)b * O_ * HW_;
    #pragma unroll
    for (int nf = 0; nf < 8; ++nf) {
        int o = wn*64 + nf*8 + tig*2;
        float bv0 = bias[o], bv1 = bias[o+1];
        #pragma unroll
        for (int mf = 0; mf < 4; ++mf) {
            int m = pixbase + wm*64 + mf*16 + grp;
            outb[(size_t)o*HW_ + m]         = acc[mf][nf][0] + bv0;
            outb[(size_t)(o+1)*HW_ + m]     = acc[mf][nf][1] + bv1;
            outb[(size_t)o*HW_ + m + 8]     = acc[mf][nf][2] + bv0;
            outb[(size_t)(o+1)*HW_ + m + 8] = acc[mf][nf][3] + bv1;
        }
    }
}

// ------------------------------------------------------------------
// launch: 3 serial launches. No streams, no events, no allocations.
// ------------------------------------------------------------------
extern "C" void kernel_launch(void* const* d_in, const int* in_sizes, int n_in,
                              void* d_out, int out_size) {
    (void)in_sizes; (void)n_in; (void)out_size;
    const float* x    = (const float*)d_in[0];
    const float* w    = (const float*)d_in[1];
    const float* bias = (const float*)d_in[2];
    float* out = (float*)d_out;

    cudaFuncSetAttribute(k_gemm, cudaFuncAttributeMaxDynamicSharedMemorySize, GEMM_SMEM);

    k_wt<<<(K_*O_ + 255)/256, 256>>>(w);
    k_dir<<<NPLANE, 128>>>(x);

    dim3 grid(HW_/BM, B_);
    k_gemm<<<grid, 256, GEMM_SMEM>>>(x, bias, out);
}

// round 12
// speedup vs baseline: 1.2450x; 1.2450x over previous
#include <cuda_runtime.h>
#include <cuda_fp16.h>
#include <cstdint>

#define B_ 8
#define C_ 256
#define H_ 128
#define W_ 128
#define HW_ (H_*W_)            // 16384
#define NPLANE (B_*C_)         // 2048
#define K_ 1280
#define O_ 256

#define NEG_INF __int_as_float(0xff800000)

// fp16 scratch: x copy + 4 directional-max tensors + transposed weights.
__device__ __half g_x16[NPLANE*HW_];
__device__ __half g_dir16[4][NPLANE*HW_];
__device__ __half g_wT16[K_*O_];

// ------------------------------------------------------------------
// helpers
// ------------------------------------------------------------------
__device__ __forceinline__ uint32_t smem_u32(const void* p) {
    return (uint32_t)__cvta_generic_to_shared(p);
}
__device__ __forceinline__ void cp16(uint32_t s, const void* g) {
    asm volatile("cp.async.cg.shared.global [%0], [%1], 16;\n" :: "r"(s), "l"(g));
}
__device__ __forceinline__ void ldsm_x4_t(uint32_t& d0, uint32_t& d1,
                                          uint32_t& d2, uint32_t& d3, uint32_t a) {
    asm volatile("ldmatrix.sync.aligned.m8n8.x4.trans.shared.b16 {%0,%1,%2,%3},[%4];\n"
                 : "=r"(d0), "=r"(d1), "=r"(d2), "=r"(d3) : "r"(a));
}
__device__ __forceinline__ void mma_f16(float* d, const uint32_t* a, const uint32_t* b) {
    asm volatile(
        "mma.sync.aligned.m16n8k16.row.col.f32.f16.f16.f32 "
        "{%0,%1,%2,%3},{%4,%5,%6,%7},{%8,%9},{%0,%1,%2,%3};"
        : "+f"(d[0]), "+f"(d[1]), "+f"(d[2]), "+f"(d[3])
        : "r"(a[0]), "r"(a[1]), "r"(a[2]), "r"(a[3]), "r"(b[0]), "r"(b[1]));
}
__device__ __forceinline__ uint32_t h2u(__half2 h) {
    return *reinterpret_cast<uint32_t*>(&h);
}

// ------------------------------------------------------------------
// kernel 0: transpose conv_w [O][K] -> wT16 [K][O]
// ------------------------------------------------------------------
__global__ void k_wt(const float* __restrict__ w) {
    int idx = blockIdx.x * 256 + threadIdx.x;
    if (idx < K_*O_) {
        int o = idx / K_;
        int k = idx - o*K_;
        g_wT16[k*O_ + o] = __float2half_rn(w[idx]);
    }
}

// ------------------------------------------------------------------
// kernel 1: all 4 directional maxes + x16, one plane per CTA, full grid.
// fp16 plane in smem (cvt is monotonic -> fp16 scans == fp32 scans + cvt).
// After one barrier: warps 0-1 H-prefix (column pairs, HMAX2),
// warps 2-3 H-suffix, warps 4-7 W-scans (shuffle) -- all concurrent.
// ------------------------------------------------------------------
#define SP_LD 132   // halves per smem row (264B: 8B-aligned, conflict-free)

__global__ void __launch_bounds__(256) k_dir(const float* __restrict__ x) {
    __shared__ __half sp[H_*SP_LD];
    int plane = blockIdx.x;
    const float* src = x + (size_t)plane*HW_;
    __half* x16 = g_x16 + (size_t)plane*HW_;
    int tid = threadIdx.x;

    // ---- load: float4 -> fp16 smem + fp16 global copy ----
    #pragma unroll
    for (int i = 0; i < 16; ++i) {
        int c = tid + i*256;               // float4 index 0..4095
        int h = c >> 5, f4 = c & 31;       // 32 float4 per row
        float4 v = __ldg(reinterpret_cast<const float4*>(src) + c);
        __half2 a = __floats2half2_rn(v.x, v.y);
        __half2 b = __floats2half2_rn(v.z, v.w);
        uint2 u = make_uint2(h2u(a), h2u(b));
        *reinterpret_cast<uint2*>(x16 + (size_t)c*4) = u;
        *reinterpret_cast<uint2*>(sp + h*SP_LD + f4*4) = u;
    }
    __syncthreads();

    int warp = tid >> 5, lane = tid & 31;
    const __half2 ninf2 = __floats2half2_rn(NEG_INF, NEG_INF);

    if (warp < 2) {
        // H-prefix, column pair 2t
        int t = tid;                       // 0..63
        __half* d0 = g_dir16[0] + (size_t)plane*HW_;
        __half2 m = ninf2;
        #pragma unroll 8
        for (int h = 0; h < H_; ++h) {
            m = __hmax2(m, *reinterpret_cast<__half2*>(sp + h*SP_LD + 2*t));
            *reinterpret_cast<__half2*>(d0 + h*W_ + 2*t) = m;
        }
    } else if (warp < 4) {
        // H-suffix, column pair 2t
        int t = tid - 64;                  // 0..63
        __half* d1 = g_dir16[1] + (size_t)plane*HW_;
        __half2 m = ninf2;
        #pragma unroll 8
        for (int h = H_-1; h >= 0; --h) {
            m = __hmax2(m, *reinterpret_cast<__half2*>(sp + h*SP_LD + 2*t));
            *reinterpret_cast<__half2*>(d1 + h*W_ + 2*t) = m;
        }
    } else {
        // W-scans: warp handles 32 rows
        __half* d2 = g_dir16[2] + (size_t)plane*HW_;
        __half* d3 = g_dir16[3] + (size_t)plane*HW_;
        for (int r = 0; r < 32; ++r) {
            int h = (warp - 4)*32 + r;
            uint2 u = *reinterpret_cast<uint2*>(sp + h*SP_LD + 4*lane);
            float2 f0 = __half22float2(*reinterpret_cast<__half2*>(&u.x));
            float2 f1 = __half22float2(*reinterpret_cast<__half2*>(&u.y));
            float v0 = f0.x, v1 = f0.y, v2 = f1.x, v3 = f1.y;

            // prefix (left->right)
            float p0 = v0, p1 = fmaxf(v1,p0), p2 = fmaxf(v2,p1), p3 = fmaxf(v3,p2);
            float agg = p3;
            #pragma unroll
            for (int d = 1; d < 32; d <<= 1) {
                float t = __shfl_up_sync(0xffffffffu, agg, d);
                if (lane >= d) agg = fmaxf(agg, t);
            }
            float prev = __shfl_up_sync(0xffffffffu, agg, 1);
            if (lane == 0) prev = NEG_INF;
            __half2 P01 = __floats2half2_rn(fmaxf(p0,prev), fmaxf(p1,prev));
            __half2 P23 = __floats2half2_rn(fmaxf(p2,prev), fmaxf(p3,prev));
            *reinterpret_cast<uint2*>(d2 + h*W_ + 4*lane) =
                make_uint2(h2u(P01), h2u(P23));

            // suffix (right->left)
            float s3 = v3, s2 = fmaxf(v2,s3), s1 = fmaxf(v1,s2), s0 = fmaxf(v0,s1);
            float agg2 = s0;
            #pragma unroll
            for (int d = 1; d < 32; d <<= 1) {
                float t = __shfl_down_sync(0xffffffffu, agg2, d);
                if (lane + d < 32) agg2 = fmaxf(agg2, t);
            }
            float nxt = __shfl_down_sync(0xffffffffu, agg2, 1);
            if (lane == 31) nxt = NEG_INF;
            __half2 S01 = __floats2half2_rn(fmaxf(s0,nxt), fmaxf(s1,nxt));
            __half2 S23 = __floats2half2_rn(fmaxf(s2,nxt), fmaxf(s3,nxt));
            *reinterpret_cast<uint2*>(d3 + h*W_ + 4*lane) =
                make_uint2(h2u(S01), h2u(S23));
        }
    }
}

// ------------------------------------------------------------------
// kernel 2: fp16 GEMM, ALL batches in one launch (R10-proven, unchanged).
// ------------------------------------------------------------------
#define BM 128
#define BN 256
#define BK 32
#define STAGES 3
#define SA_LD 136
#define SB_LD 264
#define STG_HALVES (BK*SA_LD + BK*SB_LD)
#define GEMM_SMEM (STAGES*STG_HALVES*2)   // 76800 B

__global__ void __launch_bounds__(256, 1) k_gemm(const float* __restrict__ bias,
                                                 float* __restrict__ out) {
    extern __shared__ __half sm[];

    int tid  = threadIdx.x;
    int lane = tid & 31, warp = tid >> 5;
    int wm = warp >> 2, wn = warp & 3;
    int grp = lane >> 2, tig = lane & 3;
    int lr = lane & 7, lg = lane >> 3;

    int pixbase = blockIdx.x * BM;
    int b       = blockIdx.y;

    size_t boff = (size_t)b * C_ * HW_;
    const __half* srcs[5] = { g_x16 + boff, g_dir16[0] + boff, g_dir16[1] + boff,
                              g_dir16[2] + boff, g_dir16[3] + boff };

    auto load_tile = [&](int kt, int st) {
        int region = kt >> 3;
        int c0 = (kt & 7) * BK;
        const __half* aptr = srcs[region] + (size_t)c0*HW_ + pixbase;
        const __half* bptr = g_wT16 + (size_t)(kt*BK)*O_;
        __half* sa = sm + st*STG_HALVES;
        __half* sb = sa + BK*SA_LD;
        #pragma unroll
        for (int i = 0; i < 2; ++i) {
            int c  = tid + i*256;
            int kr = c >> 4, cc = c & 15;
            cp16(smem_u32(sa + kr*SA_LD + cc*8), aptr + (size_t)kr*HW_ + cc*8);
        }
        #pragma unroll
        for (int i = 0; i < 4; ++i) {
            int c  = tid + i*256;
            int kr = c >> 5, cc = c & 31;
            cp16(smem_u32(sb + kr*SB_LD + cc*8), bptr + kr*O_ + cc*8);
        }
        asm volatile("cp.async.commit_group;\n" ::: "memory");
    };

    float acc[4][8][4];
    #pragma unroll
    for (int i = 0; i < 4; ++i)
        #pragma unroll
        for (int j = 0; j < 8; ++j)
            #pragma unroll
            for (int r = 0; r < 4; ++r) acc[i][j][r] = 0.f;

    load_tile(0, 0);
    load_tile(1, 1);

    for (int kt = 0; kt < 40; ++kt) {
        int cur = kt % STAGES;
        if (kt + 2 < 40) {
            load_tile(kt + 2, (kt + 2) % STAGES);
            asm volatile("cp.async.wait_group 2;\n" ::: "memory");
        } else {
            asm volatile("cp.async.wait_group %0;\n" :: "n"(0) : "memory");
        }
        __syncthreads();

        uint32_t saU = smem_u32(sm + cur*STG_HALVES);
        uint32_t sbU = saU + BK*SA_LD*2;

        uint32_t af[2][4][4];
        uint32_t bf[2][8][2];
        #pragma unroll
        for (int s = 0; s < 2; ++s) {
            int k0 = s*16;
            {
                int krow = k0 + lr + ((lg & 2) << 2);
                int cofs = (lg & 1) << 3;
                #pragma unroll
                for (int mf = 0; mf < 4; ++mf) {
                    int m0 = wm*64 + mf*16;
                    uint32_t a = saU + (uint32_t)(krow*SA_LD + m0 + cofs)*2;
                    ldsm_x4_t(af[s][mf][0], af[s][mf][1], af[s][mf][2], af[s][mf][3], a);
                }
            }
            {
                int krow = k0 + lr + ((lg & 1) << 3);
                int cofs = (lg >> 1) << 3;
                #pragma unroll
                for (int jp = 0; jp < 4; ++jp) {
                    int nj = wn*64 + jp*16;
                    uint32_t a = sbU + (uint32_t)(krow*SB_LD + nj + cofs)*2;
                    ldsm_x4_t(bf[s][2*jp][0], bf[s][2*jp][1],
                              bf[s][2*jp+1][0], bf[s][2*jp+1][1], a);
                }
            }
        }
        #pragma unroll
        for (int s = 0; s < 2; ++s)
            #pragma unroll
            for (int mf = 0; mf < 4; ++mf)
                #pragma unroll
                for (int nf = 0; nf < 8; ++nf)
                    mma_f16(acc[mf][nf], af[s][mf], bf[s][nf]);
        __syncthreads();
    }

    float* outb = out + (size_t)b * O_ * HW_;
    #pragma unroll
    for (int nf = 0; nf < 8; ++nf) {
        int o = wn*64 + nf*8 + tig*2;
        float bv0 = bias[o], bv1 = bias[o+1];
        #pragma unroll
        for (int mf = 0; mf < 4; ++mf) {
            int m = pixbase + wm*64 + mf*16 + grp;
            outb[(size_t)o*HW_ + m]         = acc[mf][nf][0] + bv0;
            outb[(size_t)(o+1)*HW_ + m]     = acc[mf][nf][1] + bv1;
            outb[(size_t)o*HW_ + m + 8]     = acc[mf][nf][2] + bv0;
            outb[(size_t)(o+1)*HW_ + m + 8] = acc[mf][nf][3] + bv1;
        }
    }
}

// ------------------------------------------------------------------
// launch: 3 serial launches. No streams, no events, no allocations.
// ------------------------------------------------------------------
extern "C" void kernel_launch(void* const* d_in, const int* in_sizes, int n_in,
                              void* d_out, int out_size) {
    (void)in_sizes; (void)n_in; (void)out_size;
    const float* x    = (const float*)d_in[0];
    const float* w    = (const float*)d_in[1];
    const float* bias = (const float*)d_in[2];
    float* out = (float*)d_out;

    cudaFuncSetAttribute(k_gemm, cudaFuncAttributeMaxDynamicSharedMemorySize, GEMM_SMEM);

    k_wt<<<(K_*O_ + 255)/256, 256>>>(w);
    k_dir<<<NPLANE, 256>>>(x);

    dim3 grid(HW_/BM, B_);
    k_gemm<<<grid, 256, GEMM_SMEM>>>(bias, out);
}